// round 1
// baseline (speedup 1.0000x reference)
#include <cuda_runtime.h>
#include <cuda_bf16.h>
#include <math.h>

#define Bdim 128
#define Tdim 1024
#define Hdim 512
#define BH   (Bdim * Hdim)

// ---------------- packed f32x2 helpers ----------------
__device__ __forceinline__ unsigned long long pk2(float lo, float hi) {
    unsigned long long r;
    asm("mov.b64 %0, {%1,%2};" : "=l"(r) : "f"(lo), "f"(hi));
    return r;
}
__device__ __forceinline__ unsigned long long fma2(unsigned long long a,
                                                   unsigned long long b,
                                                   unsigned long long c) {
    unsigned long long d;
    asm("fma.rn.f32x2 %0, %1, %2, %3;" : "=l"(d) : "l"(a), "l"(b), "l"(c));
    return d;
}
__device__ __forceinline__ void unpk(unsigned long long v, float& a, float& b) {
    asm("mov.b64 {%0,%1}, %2;" : "=f"(a), "=f"(b) : "l"(v));
}

// ================= Phase A: Z = X @ Wx + bias =================
// X: [B,T,H] row m = b*T + t (row contiguous in k)
// out: [T,B,H] row t*B + b
// Tiles: BM=64, BN=64, BK=32, 256 threads, 4x4 per thread, f32x2 packed.
__global__ void __launch_bounds__(256) gemm_zx(const float* __restrict__ X,
                                               const float* __restrict__ Wx,
                                               const float* __restrict__ bias,
                                               float* __restrict__ out) {
    __shared__ float As[32 * 68];  // [k][row], stride 68 (16B-aligned, conflict-mitigated)
    __shared__ float Bs[32 * 64];  // [k][col]

    const int tid = threadIdx.x;
    const int tx = tid & 15;       // col group
    const int ty = tid >> 4;       // row group
    const int m0 = blockIdx.y * 64;
    const int n0 = blockIdx.x * 64;

    unsigned long long acc[4][2];
#pragma unroll
    for (int r = 0; r < 4; r++) { acc[r][0] = 0ull; acc[r][1] = 0ull; }

    const int a_row = tid >> 3;         // 0..31
    const int a_k4  = (tid & 7) * 4;    // 0..28
    const int b_k   = tid >> 4;         // 0..15
    const int b_c4  = (tid & 15) * 4;   // 0..60

    for (int kb = 0; kb < Hdim; kb += 32) {
        // load A tile (transpose to [k][row])
#pragma unroll
        for (int pass = 0; pass < 2; pass++) {
            int row = a_row + pass * 32;
            float4 v = *(const float4*)&X[(size_t)(m0 + row) * Hdim + kb + a_k4];
            As[(a_k4 + 0) * 68 + row] = v.x;
            As[(a_k4 + 1) * 68 + row] = v.y;
            As[(a_k4 + 2) * 68 + row] = v.z;
            As[(a_k4 + 3) * 68 + row] = v.w;
        }
        // load B tile [k][col]
#pragma unroll
        for (int pass = 0; pass < 2; pass++) {
            int k = b_k + pass * 16;
            *(float4*)&Bs[k * 64 + b_c4] =
                *(const float4*)&Wx[(size_t)(kb + k) * Hdim + n0 + b_c4];
        }
        __syncthreads();

#pragma unroll
        for (int k = 0; k < 32; k++) {
            float4 a4 = *(const float4*)&As[k * 68 + ty * 4];
            ulonglong2 bv = *(const ulonglong2*)&Bs[k * 64 + tx * 4];
            unsigned long long s;
            s = pk2(a4.x, a4.x); acc[0][0] = fma2(s, bv.x, acc[0][0]); acc[0][1] = fma2(s, bv.y, acc[0][1]);
            s = pk2(a4.y, a4.y); acc[1][0] = fma2(s, bv.x, acc[1][0]); acc[1][1] = fma2(s, bv.y, acc[1][1]);
            s = pk2(a4.z, a4.z); acc[2][0] = fma2(s, bv.x, acc[2][0]); acc[2][1] = fma2(s, bv.y, acc[2][1]);
            s = pk2(a4.w, a4.w); acc[3][0] = fma2(s, bv.x, acc[3][0]); acc[3][1] = fma2(s, bv.y, acc[3][1]);
        }
        __syncthreads();
    }

    float4 bs4 = *(const float4*)&bias[n0 + tx * 4];
#pragma unroll
    for (int r = 0; r < 4; r++) {
        int m = m0 + ty * 4 + r;
        int t = m & (Tdim - 1);
        int b = m >> 10;
        float4 o;
        float x0, x1, x2, x3;
        unpk(acc[r][0], x0, x1);
        unpk(acc[r][1], x2, x3);
        o.x = x0 + bs4.x; o.y = x1 + bs4.y; o.z = x2 + bs4.z; o.w = x3 + bs4.w;
        *(float4*)&out[((size_t)t * Bdim + b) * Hdim + n0 + tx * 4] = o;
    }
}

// ================= Phase B: persistent recurrent kernel =================
__device__ unsigned g_cnt = 0;
__device__ unsigned g_gen = 0;

__device__ __forceinline__ void grid_bar() {
    __syncthreads();
    if (threadIdx.x == 0) {
        unsigned g = *(volatile unsigned*)&g_gen;
        __threadfence();
        if (atomicAdd(&g_cnt, 1u) == 127u) {
            g_cnt = 0;
            __threadfence();
            *(volatile unsigned*)&g_gen = g + 1u;
        } else {
            while (*(volatile unsigned*)&g_gen == g) __nanosleep(64);
        }
    }
    __syncthreads();
}

// grid: 128 blocks x 128 threads. Block tile: 16 rows x 32 cols of h.
//   block -> rt = bid>>4 (row tile 0..7), ct = bid&15 (col tile 0..15)
//   thread -> lane = col within tile, wg = warp -> 4 rows
// SMEM: whs (Wh column tile, loaded ONCE, layout [kg][lane*4 + j]) 64KB
//       hs  (h tile rows, [r][k] stride 520) 33KB
__global__ void __launch_bounds__(128, 1)
rnn_steps_kernel(float* __restrict__ out, const float* __restrict__ Wh,
                 const float* __restrict__ h0) {
    extern __shared__ float sm[];
    float* whs = sm;            // 16384 floats
    float* hs  = sm + 16384;    // 16 * 520 floats

    const int tid  = threadIdx.x;
    const int lane = tid & 31;
    const int wg   = tid >> 5;
    const int bid  = blockIdx.x;
    const int rt   = bid >> 4;
    const int ct   = bid & 15;
    const int row0 = rt * 16;
    const int col  = ct * 32 + lane;
    const int rb   = wg * 4;    // local row base for this warp

    // Load Wh column tile once: whs[(k>>2)*128 + lane*4 + (k&3)] = Wh[k][col]
    for (int k = wg; k < Hdim; k += 4)
        whs[(k >> 2) * 128 + lane * 4 + wg] = Wh[(size_t)k * Hdim + col];

    const float* hprev = h0;  // state0 [B,H]

    for (int t = 0; t < Tdim; t++) {
        // refill h tile (16 rows x 512) from hprev, coalesced float4
        for (int p = tid; p < 2048; p += 128) {
            int r = p >> 7;
            int q = (p & 127) << 2;
            *(float4*)&hs[r * 520 + q] =
                *(const float4*)&hprev[(size_t)(row0 + r) * Hdim + q];
        }
        // pre-load z (written by Phase A) while smem fill is in flight
        const size_t zb = (size_t)t * BH + (size_t)(row0 + rb) * Hdim + col;
        float zv0 = out[zb];
        float zv1 = out[zb + Hdim];
        float zv2 = out[zb + 2 * Hdim];
        float zv3 = out[zb + 3 * Hdim];
        __syncthreads();

        unsigned long long a0 = 0, a1 = 0, a2 = 0, a3 = 0;
#pragma unroll 2
        for (int kg = 0; kg < 128; kg++) {
            ulonglong2 wv = *(const ulonglong2*)&whs[kg * 128 + lane * 4];
            ulonglong2 h;
            h = *(const ulonglong2*)&hs[(rb + 0) * 520 + kg * 4];
            a0 = fma2(h.x, wv.x, a0); a0 = fma2(h.y, wv.y, a0);
            h = *(const ulonglong2*)&hs[(rb + 1) * 520 + kg * 4];
            a1 = fma2(h.x, wv.x, a1); a1 = fma2(h.y, wv.y, a1);
            h = *(const ulonglong2*)&hs[(rb + 2) * 520 + kg * 4];
            a2 = fma2(h.x, wv.x, a2); a2 = fma2(h.y, wv.y, a2);
            h = *(const ulonglong2*)&hs[(rb + 3) * 520 + kg * 4];
            a3 = fma2(h.x, wv.x, a3); a3 = fma2(h.y, wv.y, a3);
        }

        float x, y;
        unpk(a0, x, y); float s0 = tanhf(zv0 + x + y);
        unpk(a1, x, y); float s1 = tanhf(zv1 + x + y);
        unpk(a2, x, y); float s2 = tanhf(zv2 + x + y);
        unpk(a3, x, y); float s3 = tanhf(zv3 + x + y);

        out[zb]            = s0;
        out[zb + Hdim]     = s1;
        out[zb + 2 * Hdim] = s2;
        out[zb + 3 * Hdim] = s3;

        hprev = out + (size_t)t * BH;

        if (t != Tdim - 1) {
            __threadfence();
            grid_bar();
        }
    }
}

// ================= launch =================
extern "C" void kernel_launch(void* const* d_in, const int* in_sizes, int n_in,
                              void* d_out, int out_size) {
    const float* X    = (const float*)d_in[0];  // [B,T,H]
    const float* h0   = (const float*)d_in[1];  // [1,B,H]
    const float* Wx   = (const float*)d_in[2];  // [H,H]
    const float* Wh   = (const float*)d_in[3];  // [H,H]
    const float* bias = (const float*)d_in[4];  // [H]
    float* out = (float*)d_out;                 // [T,B,H]

    dim3 gA(Hdim / 64, (Bdim * Tdim) / 64);
    gemm_zx<<<gA, 256>>>(X, Wx, bias, out);

    const int smB = (16384 + 16 * 520) * (int)sizeof(float);  // 98,816 B
    cudaFuncSetAttribute(rnn_steps_kernel,
                         cudaFuncAttributeMaxDynamicSharedMemorySize, smB);
    rnn_steps_kernel<<<128, 128, smB>>>(out, Wh, h0);
}

// round 3
// speedup vs baseline: 1.0017x; 1.0017x over previous
#include <cuda_runtime.h>
#include <cuda_bf16.h>
#include <math.h>

#define Bdim 128
#define Tdim 1024
#define Hdim 512
#define BH   (Bdim * Hdim)

typedef unsigned long long ull;

// ---------------- packed f32x2 helpers ----------------
__device__ __forceinline__ ull pk2(float lo, float hi) {
    ull r;
    asm("mov.b64 %0, {%1,%2};" : "=l"(r) : "f"(lo), "f"(hi));
    return r;
}
__device__ __forceinline__ ull fma2(ull a, ull b, ull c) {
    ull d;
    asm("fma.rn.f32x2 %0, %1, %2, %3;" : "=l"(d) : "l"(a), "l"(b), "l"(c));
    return d;
}
__device__ __forceinline__ void unpk(ull v, float& a, float& b) {
    asm("mov.b64 {%0,%1}, %2;" : "=f"(a), "=f"(b) : "l"(v));
}

// ================= Phase A: Z = X @ Wx + bias =================
// X: [B,T,H] row m = b*T + t. out: [T,B,H] row t*B + b.
// BM=128, BN=64, BK=32, 256 threads, 8x4 outputs/thread via f32x2.
__global__ void __launch_bounds__(256) gemm_zx(const float* __restrict__ X,
                                               const float* __restrict__ Wx,
                                               const float* __restrict__ bias,
                                               float* __restrict__ out) {
    __shared__ float As[32 * 132];  // [k][row] (128 rows, pad 132)
    __shared__ float Bs[32 * 64];   // [k][col]

    const int tid = threadIdx.x;
    const int tx = tid & 15;        // col group (4 cols)
    const int ty = tid >> 4;        // row group (8 rows)
    const int m0 = blockIdx.y * 128;
    const int n0 = blockIdx.x * 64;

    ull acc[8][2];
#pragma unroll
    for (int r = 0; r < 8; r++) { acc[r][0] = 0ull; acc[r][1] = 0ull; }

    const int a_row = tid >> 3;          // 0..31
    const int a_k4  = (tid & 7) * 4;     // 0..28
    const int b_k   = tid >> 4;          // 0..15
    const int b_c4  = (tid & 15) * 4;    // 0..60

    for (int kb = 0; kb < Hdim; kb += 32) {
#pragma unroll
        for (int pass = 0; pass < 4; pass++) {
            int row = a_row + pass * 32;
            float4 v = *(const float4*)&X[(size_t)(m0 + row) * Hdim + kb + a_k4];
            As[(a_k4 + 0) * 132 + row] = v.x;
            As[(a_k4 + 1) * 132 + row] = v.y;
            As[(a_k4 + 2) * 132 + row] = v.z;
            As[(a_k4 + 3) * 132 + row] = v.w;
        }
#pragma unroll
        for (int pass = 0; pass < 2; pass++) {
            int k = b_k + pass * 16;
            *(float4*)&Bs[k * 64 + b_c4] =
                *(const float4*)&Wx[(size_t)(kb + k) * Hdim + n0 + b_c4];
        }
        __syncthreads();

#pragma unroll
        for (int k = 0; k < 32; k++) {
            float4 a0 = *(const float4*)&As[k * 132 + ty * 8];
            float4 a1 = *(const float4*)&As[k * 132 + ty * 8 + 4];
            ulonglong2 bv = *(const ulonglong2*)&Bs[k * 64 + tx * 4];
            ull s;
            s = pk2(a0.x, a0.x); acc[0][0] = fma2(s, bv.x, acc[0][0]); acc[0][1] = fma2(s, bv.y, acc[0][1]);
            s = pk2(a0.y, a0.y); acc[1][0] = fma2(s, bv.x, acc[1][0]); acc[1][1] = fma2(s, bv.y, acc[1][1]);
            s = pk2(a0.z, a0.z); acc[2][0] = fma2(s, bv.x, acc[2][0]); acc[2][1] = fma2(s, bv.y, acc[2][1]);
            s = pk2(a0.w, a0.w); acc[3][0] = fma2(s, bv.x, acc[3][0]); acc[3][1] = fma2(s, bv.y, acc[3][1]);
            s = pk2(a1.x, a1.x); acc[4][0] = fma2(s, bv.x, acc[4][0]); acc[4][1] = fma2(s, bv.y, acc[4][1]);
            s = pk2(a1.y, a1.y); acc[5][0] = fma2(s, bv.x, acc[5][0]); acc[5][1] = fma2(s, bv.y, acc[5][1]);
            s = pk2(a1.z, a1.z); acc[6][0] = fma2(s, bv.x, acc[6][0]); acc[6][1] = fma2(s, bv.y, acc[6][1]);
            s = pk2(a1.w, a1.w); acc[7][0] = fma2(s, bv.x, acc[7][0]); acc[7][1] = fma2(s, bv.y, acc[7][1]);
        }
        __syncthreads();
    }

    float4 bs4 = *(const float4*)&bias[n0 + tx * 4];
#pragma unroll
    for (int r = 0; r < 8; r++) {
        int m = m0 + ty * 8 + r;
        int t = m & (Tdim - 1);
        int b = m >> 10;
        float x0, x1, x2, x3;
        unpk(acc[r][0], x0, x1);
        unpk(acc[r][1], x2, x3);
        float4 o;
        o.x = x0 + bs4.x; o.y = x1 + bs4.y; o.z = x2 + bs4.z; o.w = x3 + bs4.w;
        *(float4*)&out[((size_t)t * Bdim + b) * Hdim + n0 + tx * 4] = o;
    }
}

// ================= Phase B: persistent recurrent kernel =================
__device__ unsigned g_cnt = 0;
__device__ unsigned g_gen = 0;

__device__ __forceinline__ void grid_bar() {
    __syncthreads();
    if (threadIdx.x == 0) {
        unsigned g = *(volatile unsigned*)&g_gen;
        __threadfence();
        if (atomicAdd(&g_cnt, 1u) == 127u) {
            g_cnt = 0;
            __threadfence();
            *(volatile unsigned*)&g_gen = g + 1u;
        } else {
            while (*(volatile unsigned*)&g_gen == g) __nanosleep(64);
        }
    }
    __syncthreads();
}

// 128 blocks x 128 threads. Block tile: 8 batch-rows x 64 cols.
//   bid>>3 -> row tile (16 tiles of 8 rows); bid&7 -> col tile (8 tiles of 64)
//   warp w: g = w&1 (col group of 32), kh = w>>1 (k half of 256)
//   lane: cp = lane&15 (col pos), kp = lane>>4 (k quarter within half)
//   lane owns 2 cols (cp, cp+16) within its col group; per-lane k range = 128.
// Reduction: shfl_xor(16) merges kp halves; smem merges kh warp pairs.
// SMEM: whs 128KB (Wh tile in exact lane-load order), hs 8x520, red 512.
__global__ void __launch_bounds__(128, 1)
rnn_steps_kernel(float* __restrict__ out, const float* __restrict__ Wh,
                 const float* __restrict__ h0) {
    extern __shared__ float sm[];
    float* whs = sm;                    // 32768 floats
    float* hs  = sm + 32768;            // 8*520
    float* red = sm + 32768 + 8 * 520;  // 512

    const int tid  = threadIdx.x;
    const int lane = tid & 31;
    const int w    = tid >> 5;
    const int g    = w & 1;
    const int kh   = w >> 1;
    const int cp   = lane & 15;
    const int kp   = lane >> 4;
    const int bid  = blockIdx.x;
    const int row0 = (bid >> 3) * 8;
    const int colbase = (bid & 7) * 64;
    const int col = colbase + g * 32 + kp * 16 + cp;  // this lane's output col

    // Fill whs ONCE in exact lane-load order:
    // idx(g,kg8,which,lane,j) = ((g*64+kg8)*2+which)*128 + lane*4 + j
    // content = Wh[kg8*8 + (lane>>4)*4 + j][colbase + g*32 + which*16 + (lane&15)]
    for (int i = tid; i < 32768; i += 128) {
        int j     = i & 3;
        int ln    = (i >> 2) & 31;
        int which = (i >> 7) & 1;
        int kg8   = (i >> 8) & 63;
        int gg    = i >> 14;
        int k = kg8 * 8 + (ln >> 4) * 4 + j;
        int c = colbase + gg * 32 + which * 16 + (ln & 15);
        whs[i] = Wh[(size_t)k * Hdim + c];
    }

    const float* hprev = h0;
    const int kp4 = kp * 4;
    const float* wb = whs + (size_t)(g * 64 + kh * 32) * 256;

    for (int t = 0; t < Tdim; t++) {
        // refill h tile (8 rows x 512)
        for (int p = tid; p < 1024; p += 128) {
            int r = p >> 7;
            int q = (p & 127) << 2;
            *(float4*)&hs[r * 520 + q] =
                *(const float4*)&hprev[(size_t)(row0 + r) * Hdim + q];
        }
        // preload z (hidden behind main loop); only kh==0 warps finalize
        float z[8];
        const size_t ob = (size_t)t * BH + (size_t)row0 * Hdim + col;
        if (kh == 0) {
#pragma unroll
            for (int r = 0; r < 8; r++) z[r] = out[ob + r * Hdim];
        }
        __syncthreads();

        ull a[8][2];
#pragma unroll
        for (int r = 0; r < 8; r++) { a[r][0] = 0ull; a[r][1] = 0ull; }

#pragma unroll 4
        for (int i = 0; i < 32; i++) {
            const float* wp = wb + i * 256 + lane * 4;
            ulonglong2 wv0 = *(const ulonglong2*)wp;
            ulonglong2 wv1 = *(const ulonglong2*)(wp + 128);
            const int ko = (kh * 32 + i) * 8 + kp4;
#pragma unroll
            for (int r = 0; r < 8; r++) {
                ulonglong2 hv = *(const ulonglong2*)&hs[r * 520 + ko];
                a[r][0] = fma2(hv.x, wv0.x, a[r][0]);
                a[r][0] = fma2(hv.y, wv0.y, a[r][0]);
                a[r][1] = fma2(hv.x, wv1.x, a[r][1]);
                a[r][1] = fma2(hv.y, wv1.y, a[r][1]);
            }
        }

        // kp reduction via shfl: acc[.][0] is partial for cols (c base),
        // acc[.][1] is partial for cols (c base +16) -- but which k-quarter
        // this lane computed depends on kp. Lane (kp, cp) holds:
        //   part0 = partial(col cp,     k-quarter kp)
        //   part1 = partial(col cp+16,  k-quarter kp)
        // My own col is cp + kp*16, so my partial is (kp ? part1 : part0);
        // my partner (lane^16) needs the other one.
        float v[8];
#pragma unroll
        for (int r = 0; r < 8; r++) {
            float x0, y0, x1, y1;
            unpk(a[r][0], x0, y0);
            unpk(a[r][1], x1, y1);
            float part0 = x0 + y0;
            float part1 = x1 + y1;
            float mine  = kp ? part1 : part0;
            float other = kp ? part0 : part1;
            v[r] = mine + __shfl_xor_sync(0xffffffffu, other, 16);
        }

        if (kh == 1) {
#pragma unroll
            for (int r = 0; r < 8; r++)
                red[(g * 8 + r) * 32 + lane] = v[r];
        }
        __syncthreads();
        if (kh == 0) {
#pragma unroll
            for (int r = 0; r < 8; r++) {
                float val = v[r] + red[(g * 8 + r) * 32 + lane] + z[r];
                out[ob + r * Hdim] = tanhf(val);
            }
        }

        hprev = out + (size_t)t * BH;
        if (t != Tdim - 1) {
            __threadfence();
            grid_bar();
        }
    }
}

// ================= launch =================
extern "C" void kernel_launch(void* const* d_in, const int* in_sizes, int n_in,
                              void* d_out, int out_size) {
    const float* X    = (const float*)d_in[0];  // [B,T,H]
    const float* h0   = (const float*)d_in[1];  // [1,B,H]
    const float* Wx   = (const float*)d_in[2];  // [H,H]
    const float* Wh   = (const float*)d_in[3];  // [H,H]
    const float* bias = (const float*)d_in[4];  // [H]
    float* out = (float*)d_out;                 // [T,B,H]

    dim3 gA(Hdim / 64, (Bdim * Tdim) / 128);
    gemm_zx<<<gA, 256>>>(X, Wx, bias, out);

    const int smB = (32768 + 8 * 520 + 512) * (int)sizeof(float);  // ~149 KB
    cudaFuncSetAttribute(rnn_steps_kernel,
                         cudaFuncAttributeMaxDynamicSharedMemorySize, smB);
    rnn_steps_kernel<<<128, 128, smB>>>(out, Wh, h0);
}

// round 4
// speedup vs baseline: 1.2606x; 1.2585x over previous
#include <cuda_runtime.h>
#include <cuda_bf16.h>
#include <math.h>

#define Bdim 128
#define Tdim 1024
#define Hdim 512
#define BH   (Bdim * Hdim)

typedef unsigned long long ull;

// ---------------- packed f32x2 helpers ----------------
__device__ __forceinline__ ull pk2(float lo, float hi) {
    ull r;
    asm("mov.b64 %0, {%1,%2};" : "=l"(r) : "f"(lo), "f"(hi));
    return r;
}
__device__ __forceinline__ ull fma2(ull a, ull b, ull c) {
    ull d;
    asm("fma.rn.f32x2 %0, %1, %2, %3;" : "=l"(d) : "l"(a), "l"(b), "l"(c));
    return d;
}
__device__ __forceinline__ void unpk(ull v, float& a, float& b) {
    asm("mov.b64 {%0,%1}, %2;" : "=f"(a), "=f"(b) : "l"(v));
}

// ================= Phase A: Z = X @ Wx + bias =================
// X: [B,T,H] row m = b*T + t. out: [T,B,H] row t*B + b.
// BM=128, BN=64, BK=32, 256 threads, 8x4 outputs/thread via f32x2.
__global__ void __launch_bounds__(256) gemm_zx(const float* __restrict__ X,
                                               const float* __restrict__ Wx,
                                               const float* __restrict__ bias,
                                               float* __restrict__ out) {
    __shared__ float As[32 * 132];  // [k][row] (128 rows, pad 132)
    __shared__ float Bs[32 * 64];   // [k][col]

    const int tid = threadIdx.x;
    const int tx = tid & 15;        // col group (4 cols)
    const int ty = tid >> 4;        // row group (8 rows)
    const int m0 = blockIdx.y * 128;
    const int n0 = blockIdx.x * 64;

    ull acc[8][2];
#pragma unroll
    for (int r = 0; r < 8; r++) { acc[r][0] = 0ull; acc[r][1] = 0ull; }

    const int a_row = tid >> 3;          // 0..31
    const int a_k4  = (tid & 7) * 4;     // 0..28
    const int b_k   = tid >> 4;          // 0..15
    const int b_c4  = (tid & 15) * 4;    // 0..60

    for (int kb = 0; kb < Hdim; kb += 32) {
#pragma unroll
        for (int pass = 0; pass < 4; pass++) {
            int row = a_row + pass * 32;
            float4 v = *(const float4*)&X[(size_t)(m0 + row) * Hdim + kb + a_k4];
            As[(a_k4 + 0) * 132 + row] = v.x;
            As[(a_k4 + 1) * 132 + row] = v.y;
            As[(a_k4 + 2) * 132 + row] = v.z;
            As[(a_k4 + 3) * 132 + row] = v.w;
        }
#pragma unroll
        for (int pass = 0; pass < 2; pass++) {
            int k = b_k + pass * 16;
            *(float4*)&Bs[k * 64 + b_c4] =
                *(const float4*)&Wx[(size_t)(kb + k) * Hdim + n0 + b_c4];
        }
        __syncthreads();

#pragma unroll
        for (int k = 0; k < 32; k++) {
            float4 a0 = *(const float4*)&As[k * 132 + ty * 8];
            float4 a1 = *(const float4*)&As[k * 132 + ty * 8 + 4];
            ulonglong2 bv = *(const ulonglong2*)&Bs[k * 64 + tx * 4];
            ull s;
            s = pk2(a0.x, a0.x); acc[0][0] = fma2(s, bv.x, acc[0][0]); acc[0][1] = fma2(s, bv.y, acc[0][1]);
            s = pk2(a0.y, a0.y); acc[1][0] = fma2(s, bv.x, acc[1][0]); acc[1][1] = fma2(s, bv.y, acc[1][1]);
            s = pk2(a0.z, a0.z); acc[2][0] = fma2(s, bv.x, acc[2][0]); acc[2][1] = fma2(s, bv.y, acc[2][1]);
            s = pk2(a0.w, a0.w); acc[3][0] = fma2(s, bv.x, acc[3][0]); acc[3][1] = fma2(s, bv.y, acc[3][1]);
            s = pk2(a1.x, a1.x); acc[4][0] = fma2(s, bv.x, acc[4][0]); acc[4][1] = fma2(s, bv.y, acc[4][1]);
            s = pk2(a1.y, a1.y); acc[5][0] = fma2(s, bv.x, acc[5][0]); acc[5][1] = fma2(s, bv.y, acc[5][1]);
            s = pk2(a1.z, a1.z); acc[6][0] = fma2(s, bv.x, acc[6][0]); acc[6][1] = fma2(s, bv.y, acc[6][1]);
            s = pk2(a1.w, a1.w); acc[7][0] = fma2(s, bv.x, acc[7][0]); acc[7][1] = fma2(s, bv.y, acc[7][1]);
        }
        __syncthreads();
    }

    float4 bs4 = *(const float4*)&bias[n0 + tx * 4];
#pragma unroll
    for (int r = 0; r < 8; r++) {
        int m = m0 + ty * 8 + r;
        int t = m & (Tdim - 1);
        int b = m >> 10;
        float x0, x1, x2, x3;
        unpk(acc[r][0], x0, x1);
        unpk(acc[r][1], x2, x3);
        float4 o;
        o.x = x0 + bs4.x; o.y = x1 + bs4.y; o.z = x2 + bs4.z; o.w = x3 + bs4.w;
        *(float4*)&out[((size_t)t * Bdim + b) * Hdim + n0 + tx * 4] = o;
    }
}

// ================= Phase B: persistent recurrent kernel =================
// 16 independent clusters of 8 CTAs. Cluster c owns batch rows [c*8, c*8+8).
// CTA rank ct within cluster owns cols [ct*64, ct*64+64).
// Recurrence closes within the cluster -> only barrier.cluster per step.
//   warp w: g = w&1 (col group of 32), kh = w>>1 (k half of 256)
//   lane: cp = lane&15 (col pos), kp = lane>>4 (k quarter within half)
// Reduction: shfl_xor(16) merges kp quarters; smem merges kh warp pairs.
// SMEM: whs 128KB (Wh tile in exact lane-load order), hs 8x520, red 512.
__global__ void __launch_bounds__(128, 1) __cluster_dims__(8, 1, 1)
rnn_steps_kernel(float* __restrict__ out, const float* __restrict__ Wh,
                 const float* __restrict__ h0) {
    extern __shared__ float sm[];
    float* whs = sm;                    // 32768 floats
    float* hs  = sm + 32768;            // 8*520
    float* red = sm + 32768 + 8 * 520;  // 512

    const int tid  = threadIdx.x;
    const int lane = tid & 31;
    const int w    = tid >> 5;
    const int g    = w & 1;
    const int kh   = w >> 1;
    const int cp   = lane & 15;
    const int kp   = lane >> 4;
    const int bid  = blockIdx.x;
    const int row0 = (bid >> 3) * 8;         // cluster id * 8
    const int colbase = (bid & 7) * 64;      // cluster rank * 64
    const int col = colbase + g * 32 + kp * 16 + cp;  // this lane's output col

    // Fill whs ONCE in exact lane-load order:
    // idx(g,kg8,which,lane,j) = ((g*64+kg8)*2+which)*128 + lane*4 + j
    // content = Wh[kg8*8 + (lane>>4)*4 + j][colbase + g*32 + which*16 + (lane&15)]
    for (int i = tid; i < 32768; i += 128) {
        int j     = i & 3;
        int ln    = (i >> 2) & 31;
        int which = (i >> 7) & 1;
        int kg8   = (i >> 8) & 63;
        int gg    = i >> 14;
        int k = kg8 * 8 + (ln >> 4) * 4 + j;
        int c = colbase + gg * 32 + which * 16 + (ln & 15);
        whs[i] = Wh[(size_t)k * Hdim + c];
    }

    const float* hprev = h0;
    const int kp4 = kp * 4;
    const float* wb = whs + (size_t)(g * 64 + kh * 32) * 256;

    for (int t = 0; t < Tdim; t++) {
        // refill h tile (8 rows x 512) from hprev
        for (int p = tid; p < 1024; p += 128) {
            int r = p >> 7;
            int q = (p & 127) << 2;
            *(float4*)&hs[r * 520 + q] =
                *(const float4*)&hprev[(size_t)(row0 + r) * Hdim + q];
        }
        // preload z (written by Phase A); only kh==0 warps finalize
        float z[8];
        const size_t ob = (size_t)t * BH + (size_t)row0 * Hdim + col;
        if (kh == 0) {
#pragma unroll
            for (int r = 0; r < 8; r++) z[r] = out[ob + r * Hdim];
        }
        __syncthreads();

        ull a[8][2];
#pragma unroll
        for (int r = 0; r < 8; r++) { a[r][0] = 0ull; a[r][1] = 0ull; }

#pragma unroll 4
        for (int i = 0; i < 32; i++) {
            const float* wp = wb + i * 256 + lane * 4;
            ulonglong2 wv0 = *(const ulonglong2*)wp;
            ulonglong2 wv1 = *(const ulonglong2*)(wp + 128);
            const int ko = (kh * 32 + i) * 8 + kp4;
#pragma unroll
            for (int r = 0; r < 8; r++) {
                ulonglong2 hv = *(const ulonglong2*)&hs[r * 520 + ko];
                a[r][0] = fma2(hv.x, wv0.x, a[r][0]);
                a[r][0] = fma2(hv.y, wv0.y, a[r][0]);
                a[r][1] = fma2(hv.x, wv1.x, a[r][1]);
                a[r][1] = fma2(hv.y, wv1.y, a[r][1]);
            }
        }

        // Lane (kp, cp) holds: part0 = partial(col cp, quarter kp),
        // part1 = partial(col cp+16, quarter kp). Own col = cp + kp*16.
        float v[8];
#pragma unroll
        for (int r = 0; r < 8; r++) {
            float x0, y0, x1, y1;
            unpk(a[r][0], x0, y0);
            unpk(a[r][1], x1, y1);
            float part0 = x0 + y0;
            float part1 = x1 + y1;
            float mine  = kp ? part1 : part0;
            float other = kp ? part0 : part1;
            v[r] = mine + __shfl_xor_sync(0xffffffffu, other, 16);
        }

        if (kh == 1) {
#pragma unroll
            for (int r = 0; r < 8; r++)
                red[(g * 8 + r) * 32 + lane] = v[r];
        }
        __syncthreads();
        if (kh == 0) {
#pragma unroll
            for (int r = 0; r < 8; r++) {
                float val = v[r] + red[(g * 8 + r) * 32 + lane] + z[r];
                out[ob + r * Hdim] = tanhf(val);
            }
        }

        hprev = out + (size_t)t * BH;
        if (t != Tdim - 1) {
            // Cluster-scope release/acquire: h_t stores visible to the 7 peer
            // CTAs; also flushes L1D so next step's loads hit fresh L2 data.
            asm volatile("barrier.cluster.arrive.aligned;" ::: "memory");
            asm volatile("barrier.cluster.wait.aligned;" ::: "memory");
        }
    }
}

// ================= launch =================
extern "C" void kernel_launch(void* const* d_in, const int* in_sizes, int n_in,
                              void* d_out, int out_size) {
    const float* X    = (const float*)d_in[0];  // [B,T,H]
    const float* h0   = (const float*)d_in[1];  // [1,B,H]
    const float* Wx   = (const float*)d_in[2];  // [H,H]
    const float* Wh   = (const float*)d_in[3];  // [H,H]
    const float* bias = (const float*)d_in[4];  // [H]
    float* out = (float*)d_out;                 // [T,B,H]

    dim3 gA(Hdim / 64, (Bdim * Tdim) / 128);
    gemm_zx<<<gA, 256>>>(X, Wx, bias, out);

    const int smB = (32768 + 8 * 520 + 512) * (int)sizeof(float);  // ~150 KB
    cudaFuncSetAttribute(rnn_steps_kernel,
                         cudaFuncAttributeMaxDynamicSharedMemorySize, smB);
    rnn_steps_kernel<<<128, 128, smB>>>(out, Wh, h0);
}